// round 1
// baseline (speedup 1.0000x reference)
#include <cuda_runtime.h>

// LiftSplatShoot voxel pooling, GB300.
// Grid: NX0 x NX1 x 1, cell 0.5 x 0.5 x 20, lo = bx - dx/2 = (-50, -50, -10).
// out[c * 40000 + gx*200 + gy] = sum over points in voxel (gx,gy) of x[p][c].

#define NX0 200
#define NX1 200
#define NCH 32
#define NVOX (NX0 * NX1)

// Scratch accumulator, voxel-major so a point's 32 channel-adds hit one 128B line.
// 200*200*32 floats = 5.12 MB (L2-resident). __device__ global per allocation rules.
static __device__ float g_scratch[NVOX * NCH];

__global__ void lss_zero_kernel() {
    int t = blockIdx.x * blockDim.x + threadIdx.x;
    if (t < NVOX * NCH / 4) {
        reinterpret_cast<float4*>(g_scratch)[t] = make_float4(0.f, 0.f, 0.f, 0.f);
    }
}

// One thread per (point, 4-channel group). t in [0, nprime*8).
// x read is a coalesced float4 (x layout is [point][channel], C=32).
__global__ void lss_scatter_kernel(const float* __restrict__ geom,
                                   const float4* __restrict__ xv,
                                   int n_items) {
    int t = blockIdx.x * blockDim.x + threadIdx.x;
    if (t >= n_items) return;

    int p = t >> 3;        // point index
    int q = t & 7;         // channel group (4 channels each)

    // geom[p] broadcast across the 8 threads of this point; L1 handles reuse.
    float px = geom[p * 3 + 0];
    float py = geom[p * 3 + 1];
    float pz = geom[p * 3 + 2];

    // Match reference exactly: IEEE add + divide, then truncate-toward-zero cast.
    // (int) on CUDA = cvt.rzi.s32.f32, same as jnp astype(int32).
    int gx = (int)__fdiv_rn(__fadd_rn(px, 50.0f), 0.5f);
    int gy = (int)__fdiv_rn(__fadd_rn(py, 50.0f), 0.5f);
    int gz = (int)__fdiv_rn(__fadd_rn(pz, 10.0f), 20.0f);

    if ((unsigned)gx < NX0 && (unsigned)gy < NX1 && gz == 0) {
        float4 v = xv[t];
        float* addr = &g_scratch[(gx * NX1 + gy) * NCH + q * 4];
        // Vectorized no-return reduction (sm_90+): one REDG.128 instead of 4 REDG.32.
        asm volatile("red.global.add.v4.f32 [%0], {%1, %2, %3, %4};"
                     :: "l"(addr), "f"(v.x), "f"(v.y), "f"(v.z), "f"(v.w)
                     : "memory");
    }
}

// scratch[vox][c] -> out[c][vox] via 32x32 shared tile; both phases coalesced.
__global__ void lss_transpose_kernel(float* __restrict__ out) {
    __shared__ float tile[32][33];
    int vox0 = blockIdx.x * 32;
    // load: threadIdx.x = channel (contiguous), threadIdx.y = voxel row
    tile[threadIdx.y][threadIdx.x] = g_scratch[(vox0 + threadIdx.y) * NCH + threadIdx.x];
    __syncthreads();
    // store: threadIdx.x = voxel offset (contiguous in out), threadIdx.y = channel
    out[threadIdx.y * NVOX + vox0 + threadIdx.x] = tile[threadIdx.x][threadIdx.y];
}

extern "C" void kernel_launch(void* const* d_in, const int* in_sizes, int n_in,
                              void* d_out, int out_size) {
    const float* in0 = (const float*)d_in[0];
    const float* in1 = (const float*)d_in[1];
    int s0 = in_sizes[0], s1 = in_sizes[1];

    // geom = nprime*3 elements, x = nprime*32 elements -> geom is the smaller.
    const float* geom;
    const float* x;
    int xsize;
    if (s0 < s1) { geom = in0; x = in1; xsize = s1; }
    else         { geom = in1; x = in0; xsize = s0; }

    int n_items = xsize / 4;  // nprime * 8 (one thread per point per 4 channels)

    lss_zero_kernel<<<(NVOX * NCH / 4 + 255) / 256, 256>>>();
    lss_scatter_kernel<<<(n_items + 255) / 256, 256>>>(
        geom, reinterpret_cast<const float4*>(x), n_items);
    lss_transpose_kernel<<<NVOX / 32, dim3(32, 32)>>>((float*)d_out);
}